// round 17
// baseline (speedup 1.0000x reference)
#include <cuda_runtime.h>
#include <cuda_fp16.h>
#include <cstdint>

namespace {

constexpr int BB = 256, TT = 512, DD = 64, HH = 128, KC = 256;
constexpr int NROW = BB * TT;            // 131072 (b,t) rows

// g_pre[row][q][j]: q = 0 zpre(+bz), 1 rpre(+br), 2 xmpre(+bh), 3 dh
__device__ float  g_pre[(size_t)NROW * 4 * HH];            // 256 MB
__device__ __half g_act[(size_t)NROW * 192];               // [row][xt|m|d]
__device__ uint2  g_wfrag[448 * 32];

__device__ __forceinline__ float2 mk2(float x, float y) { return make_float2(x, y); }

__device__ __forceinline__ unsigned pack_h2(float x, float y) {
    __half2 h = __floats2half2_rn(x, y);
    return *reinterpret_cast<unsigned*>(&h);
}

#define MMA16816(d0, d1, d2, d3, a0, a1, a2, a3, b0, b1)                     \
    asm volatile(                                                            \
        "mma.sync.aligned.m16n8k16.row.col.f32.f16.f16.f32 "                 \
        "{%0,%1,%2,%3}, {%4,%5,%6,%7}, {%8,%9}, {%0,%1,%2,%3};"              \
        : "+f"(d0), "+f"(d1), "+f"(d2), "+f"(d3)                             \
        : "r"(a0), "r"(a1), "r"(a2), "r"(a3), "r"(b0), "r"(b1))

// ===========================================================================
// P1: elementwise -> fp16 act matrix [row][ xt(64) | m(64) | d(64) ].
// ===========================================================================
__global__ void __launch_bounds__(256, 1) act_kernel(
    const float* __restrict__ inp,
    const float* __restrict__ Wgx, const float* __restrict__ bgx)
{
    const int row = blockIdx.x * 8 + (threadIdx.x >> 5);
    const int l   = threadIdx.x & 31;
    const int b = row >> 9, t = row & 511;
    const float* ib = inp + ((long)(b * 4) * TT + t) * DD;
    const long CH = (long)TT * DD;
    float2 x  = *(const float2*)(ib + 2 * l);
    float2 xl = *(const float2*)(ib + CH + 2 * l);
    float2 m  = *(const float2*)(ib + 2 * CH + 2 * l);
    float2 d  = *(const float2*)(ib + 3 * CH + 2 * l);
    float  g0 = __ldg(&Wgx[(2 * l) * DD + 2 * l]);
    float  g1 = __ldg(&Wgx[(2 * l + 1) * DD + 2 * l + 1]);
    float2 bx = *(const float2*)(bgx + 2 * l);
    float dx0 = __expf(-fmaxf(fmaf(d.x, g0, bx.x), 0.f));
    float dx1 = __expf(-fmaxf(fmaf(d.y, g1, bx.y), 0.f));
    float xt0 = m.x * x.x + (1.f - m.x) * (dx0 * xl.x);
    float xt1 = m.y * x.y + (1.f - m.y) * (dx1 * xl.y);
    __half2* ga = (__half2*)(g_act + (size_t)row * 192);
    ga[l]      = __floats2half2_rn(xt0, xt1);
    ga[32 + l] = __floats2half2_rn(m.x, m.y);
    ga[64 + l] = __floats2half2_rn(d.x, d.y);
}

// ===========================================================================
// P0: pack weights into mma B-fragment lane order (verified R11).
// ===========================================================================
__global__ void packw_kernel(const float* __restrict__ Wz,
                             const float* __restrict__ Wr,
                             const float* __restrict__ Wh,
                             const float* __restrict__ Wgh) {
    int idx = blockIdx.x * 256 + threadIdx.x;
    int fragIdx = idx >> 5, lane = idx & 31;
    if (fragIdx >= 448) return;
    int g = lane >> 2, t = lane & 3;
    uint2 v;
    if (fragIdx < 384) {
        int q   = fragIdx >> 7;
        int rem = fragIdx & 127;
        int jt = rem >> 3, kt = rem & 7;
        const float* W = (q == 0) ? Wz : (q == 1) ? Wr : Wh;
        int j = jt * 8 + g, k0 = kt * 16;
        auto src = [&](int k) {
            int col = (k < 64) ? k : k + 128;
            return W[j * KC + col];
        };
        v.x = pack_h2(src(k0 + 2 * t),     src(k0 + 2 * t + 1));
        v.y = pack_h2(src(k0 + 2 * t + 8), src(k0 + 2 * t + 9));
    } else {
        int rem = fragIdx - 384;
        int jt = rem >> 2, kt = rem & 3;
        int j = jt * 8 + g, k0 = kt * 16;
        v.x = pack_h2(Wgh[j * DD + k0 + 2 * t],     Wgh[j * DD + k0 + 2 * t + 1]);
        v.y = pack_h2(Wgh[j * DD + k0 + 2 * t + 8], Wgh[j * DD + k0 + 2 * t + 9]);
    }
    g_wfrag[fragIdx * 32 + lane] = v;
}

// ===========================================================================
// P2: HMMA GEMM (verified R11, ~90 us).
// ===========================================================================
constexpr int GS_ACT  = 0;
constexpr int GS_WF   = 51200;
constexpr int GS_BIAS = GS_WF + 114688;
constexpr int GEMM_SMEM = GS_BIAS + 512 * 4;

__global__ void __launch_bounds__(256, 1) gemm_kernel(
    const float* __restrict__ bz, const float* __restrict__ br,
    const float* __restrict__ bh, const float* __restrict__ bgh)
{
    extern __shared__ char sm[];
    __half* sact = (__half*)(sm + GS_ACT);
    uint2*  swf  = (uint2*)(sm + GS_WF);
    float*  sbias = (float*)(sm + GS_BIAS);

    const int tid = threadIdx.x;
    const int row0 = blockIdx.x * 128;

    for (int i = tid; i < 128 * 48; i += 256) {
        int r = i / 48, c = i - r * 48;
        uint2 v = *(const uint2*)(g_act + (size_t)(row0 + r) * 192 + c * 4);
        *(uint2*)(sact + r * 200 + c * 4) = v;
    }
    for (int i = tid; i < 448 * 32 / 2; i += 256)
        ((uint4*)swf)[i] = ((const uint4*)g_wfrag)[i];
    if (tid < 128) {
        sbias[tid] = bz[tid];       sbias[128 + tid] = br[tid];
        sbias[256 + tid] = bh[tid]; sbias[384 + tid] = bgh[tid];
    }
    __syncthreads();

    const int w = tid >> 5, lane = tid & 31;
    const int g = lane >> 2, t = lane & 3;
    const int arow = w * 16 + g;

    uint32_t A[12][4];
    #pragma unroll
    for (int kt = 0; kt < 12; ++kt) {
        int k0 = (kt < 8) ? kt * 16 : 128 + (kt - 8) * 16;
        const __half* p = sact + arow * 200 + k0 + 2 * t;
        A[kt][0] = *(const uint32_t*)(p);
        A[kt][1] = *(const uint32_t*)(p + 8 * 200);
        A[kt][2] = *(const uint32_t*)(p + 8);
        A[kt][3] = *(const uint32_t*)(p + 8 * 200 + 8);
    }

    for (int q = 0; q < 3; ++q) {
        #pragma unroll 4
        for (int jt = 0; jt < 16; ++jt) {
            float d0 = 0.f, d1 = 0.f, d2 = 0.f, d3 = 0.f;
            const uint2* wp = swf + (q * 128 + jt * 8) * 32 + lane;
            #pragma unroll
            for (int kt = 0; kt < 8; ++kt) {
                uint2 b = wp[kt * 32];
                MMA16816(d0, d1, d2, d3,
                         A[kt][0], A[kt][1], A[kt][2], A[kt][3], b.x, b.y);
            }
            int j0 = jt * 8 + 2 * t;
            float2 bb = *(const float2*)&sbias[q * 128 + j0];
            size_t base = (size_t)(row0 + arow) * 512 + q * 128 + j0;
            *(float2*)&g_pre[base]            = mk2(d0 + bb.x, d1 + bb.y);
            *(float2*)&g_pre[base + 8 * 512]  = mk2(d2 + bb.x, d3 + bb.y);
        }
    }
    #pragma unroll 4
    for (int jt = 0; jt < 16; ++jt) {
        float d0 = 0.f, d1 = 0.f, d2 = 0.f, d3 = 0.f;
        const uint2* wp = swf + (384 + jt * 4) * 32 + lane;
        #pragma unroll
        for (int kt = 0; kt < 4; ++kt) {
            uint2 b = wp[kt * 32];
            MMA16816(d0, d1, d2, d3,
                     A[8 + kt][0], A[8 + kt][1], A[8 + kt][2], A[8 + kt][3],
                     b.x, b.y);
        }
        int j0 = jt * 8 + 2 * t;
        float2 bb = *(const float2*)&sbias[384 + j0];
        size_t base = (size_t)(row0 + arow) * 512 + 384 + j0;
        *(float2*)&g_pre[base] =
            mk2(__expf(-fmaxf(d0 + bb.x, 0.f)), __expf(-fmaxf(d1 + bb.y, 0.f)));
        *(float2*)&g_pre[base + 8 * 512] =
            mk2(__expf(-fmaxf(d2 + bb.x, 0.f)), __expf(-fmaxf(d3 + bb.y, 0.f)));
    }
}

// ===========================================================================
// Scan v8: R16 HFMA2 structure, but 4 BATCHES PER CTA (grid 64).
// Per-step bubbles (barriers, MUFU tails) amortize over 2x the work;
// weights are shared across all 4 batch accumulations (no duplication).
// Epilogue: lane kh owns batches {kh, kh+2} (predicated selects only).
// ===========================================================================
__global__ void __launch_bounds__(256, 1) scan_kernel(
    const float* __restrict__ Wz, const float* __restrict__ Wr,
    const float* __restrict__ Wh,
    float* __restrict__ out)         // [B,T,H]
{
    __shared__ __align__(16) __half hpre16[4][2][72];
    __shared__ __align__(16) __half crh16 [4][2][72];

    const int tid = threadIdx.x;
    const int b0  = blockIdx.x * 4;
    const int j   = tid >> 1;        // output row 0..127
    const int kh  = tid & 1;         // K-half (GEMV) / batch selector (epi)

    // ---- persistent packed fp16 weight rows over h-region K-half kh ----
    __half2 wz2[32], wr2[32], wh2[32];
    {
        const int koff = 64 + kh * 64;
        #pragma unroll
        for (int i = 0; i < 32; ++i) {
            float2 a = *(const float2*)&Wz[j * KC + koff + 2 * i];
            wz2[i] = __floats2half2_rn(a.x, a.y);
            float2 b = *(const float2*)&Wr[j * KC + koff + 2 * i];
            wr2[i] = __floats2half2_rn(b.x, b.y);
            float2 c = *(const float2*)&Wh[j * KC + koff + 2 * i];
            wh2[i] = __floats2half2_rn(c.x, c.y);
        }
    }
    for (int i = tid; i < 4 * 2 * 72; i += 256) {
        ((__half*)hpre16)[i] = __float2half(0.f);
        ((__half*)crh16)[i]  = __float2half(0.f);
    }

    // scratch streams: epi lane kh owns batches A = kh, B = kh + 2
    const size_t tbA = ((size_t)(b0 + kh) * TT) * 512 + j;
    const size_t tbB = ((size_t)(b0 + kh + 2) * TT) * 512 + j;
    float pzA, prA, pxA, pdA, nzA, nrA, nxA, ndA;
    float pzB, prB, pxB, pdB, nzB, nrB, nxB, ndB;
    pzA = g_pre[tbA];       prA = g_pre[tbA + 128];
    pxA = g_pre[tbA + 256]; pdA = g_pre[tbA + 512 + 384];
    nzA = g_pre[tbA + 512]; nrA = g_pre[tbA + 512 + 128];
    nxA = g_pre[tbA + 512 + 256]; ndA = g_pre[tbA + 1024 + 384];
    pzB = g_pre[tbB];       prB = g_pre[tbB + 128];
    pxB = g_pre[tbB + 256]; pdB = g_pre[tbB + 512 + 384];
    nzB = g_pre[tbB + 512]; nrB = g_pre[tbB + 512 + 128];
    nxB = g_pre[tbB + 512 + 256]; ndB = g_pre[tbB + 1024 + 384];
    float hownA = 0.f, hownB = 0.f, zrawA = 0.f, zrawB = 0.f;
    __syncthreads();

    const __half2 hz = __float2half2_rn(0.f);

    for (int t = 0; t < TT; ++t) {
        // ---- stage A: z/r over K-half kh, ALL 4 batches ----
        {
            float2 AZ0 = mk2(0,0), AZ1 = mk2(0,0), AZ2 = mk2(0,0), AZ3 = mk2(0,0);
            float2 AR0 = mk2(0,0), AR1 = mk2(0,0), AR2 = mk2(0,0), AR3 = mk2(0,0);
            #pragma unroll
            for (int c = 0; c < 4; ++c) {              // chunk = 16 terms
                __half2 az0 = hz, az1 = hz, az2 = hz, az3 = hz;
                __half2 ar0 = hz, ar1 = hz, ar2 = hz, ar3 = hz;
                #pragma unroll
                for (int u = 0; u < 2; ++u) {
                    const int idx = 2 * c + u;
                    uint4 v0 = *(const uint4*)&hpre16[0][kh][8 * idx];
                    uint4 v1 = *(const uint4*)&hpre16[1][kh][8 * idx];
                    uint4 v2 = *(const uint4*)&hpre16[2][kh][8 * idx];
                    uint4 v3 = *(const uint4*)&hpre16[3][kh][8 * idx];
                    const __half2* p0 = (const __half2*)&v0;
                    const __half2* p1 = (const __half2*)&v1;
                    const __half2* p2 = (const __half2*)&v2;
                    const __half2* p3 = (const __half2*)&v3;
                    #pragma unroll
                    for (int q = 0; q < 4; ++q) {
                        const __half2 wz = wz2[4 * idx + q];
                        const __half2 wr = wr2[4 * idx + q];
                        az0 = __hfma2(wz, p0[q], az0);
                        az1 = __hfma2(wz, p1[q], az1);
                        az2 = __hfma2(wz, p2[q], az2);
                        az3 = __hfma2(wz, p3[q], az3);
                        ar0 = __hfma2(wr, p0[q], ar0);
                        ar1 = __hfma2(wr, p1[q], ar1);
                        ar2 = __hfma2(wr, p2[q], ar2);
                        ar3 = __hfma2(wr, p3[q], ar3);
                    }
                }
                float2 f;
                f = __half22float2(az0); AZ0.x += f.x; AZ0.y += f.y;
                f = __half22float2(az1); AZ1.x += f.x; AZ1.y += f.y;
                f = __half22float2(az2); AZ2.x += f.x; AZ2.y += f.y;
                f = __half22float2(az3); AZ3.x += f.x; AZ3.y += f.y;
                f = __half22float2(ar0); AR0.x += f.x; AR0.y += f.y;
                f = __half22float2(ar1); AR1.x += f.x; AR1.y += f.y;
                f = __half22float2(ar2); AR2.x += f.x; AR2.y += f.y;
                f = __half22float2(ar3); AR3.x += f.x; AR3.y += f.y;
            }
            float zs0 = AZ0.x + AZ0.y, zs1 = AZ1.x + AZ1.y;
            float zs2 = AZ2.x + AZ2.y, zs3 = AZ3.x + AZ3.y;
            float rs0 = AR0.x + AR0.y, rs1 = AR1.x + AR1.y;
            float rs2 = AR2.x + AR2.y, rs3 = AR3.x + AR3.y;
            zs0 += __shfl_xor_sync(0xFFFFFFFFu, zs0, 1);
            zs1 += __shfl_xor_sync(0xFFFFFFFFu, zs1, 1);
            zs2 += __shfl_xor_sync(0xFFFFFFFFu, zs2, 1);
            zs3 += __shfl_xor_sync(0xFFFFFFFFu, zs3, 1);
            rs0 += __shfl_xor_sync(0xFFFFFFFFu, rs0, 1);
            rs1 += __shfl_xor_sync(0xFFFFFFFFu, rs1, 1);
            rs2 += __shfl_xor_sync(0xFFFFFFFFu, rs2, 1);
            rs3 += __shfl_xor_sync(0xFFFFFFFFu, rs3, 1);
            // epi: lane kh handles batches kh (A) and kh+2 (B)
            zrawA = (kh ? zs1 : zs0) + pzA;            // sigmoid deferred
            zrawB = (kh ? zs3 : zs2) + pzB;
            float rpA = (kh ? rs1 : rs0) + prA;
            float rpB = (kh ? rs3 : rs2) + prB;
            float rA = __fdividef(1.f, 1.f + __expf(-rpA));
            float rB = __fdividef(1.f, 1.f + __expf(-rpB));
            crh16[kh][j >> 6][j & 63]     = __float2half(rA * hownA);
            crh16[kh + 2][j >> 6][j & 63] = __float2half(rB * hownB);
        }
        __syncthreads();                                   // bar 1

        // ---- stage C: Wh_h @ (r*hpre), K-half kh, ALL 4 batches ----
        {
            float2 C0 = mk2(0,0), C1 = mk2(0,0), C2 = mk2(0,0), C3 = mk2(0,0);
            #pragma unroll
            for (int c = 0; c < 4; ++c) {
                __half2 a0 = hz, a1 = hz, a2 = hz, a3 = hz;
                #pragma unroll
                for (int u = 0; u < 2; ++u) {
                    const int idx = 2 * c + u;
                    uint4 v0 = *(const uint4*)&crh16[0][kh][8 * idx];
                    uint4 v1 = *(const uint4*)&crh16[1][kh][8 * idx];
                    uint4 v2 = *(const uint4*)&crh16[2][kh][8 * idx];
                    uint4 v3 = *(const uint4*)&crh16[3][kh][8 * idx];
                    const __half2* p0 = (const __half2*)&v0;
                    const __half2* p1 = (const __half2*)&v1;
                    const __half2* p2 = (const __half2*)&v2;
                    const __half2* p3 = (const __half2*)&v3;
                    #pragma unroll
                    for (int q = 0; q < 4; ++q) {
                        const __half2 wh = wh2[4 * idx + q];
                        a0 = __hfma2(wh, p0[q], a0);
                        a1 = __hfma2(wh, p1[q], a1);
                        a2 = __hfma2(wh, p2[q], a2);
                        a3 = __hfma2(wh, p3[q], a3);
                    }
                }
                float2 f;
                f = __half22float2(a0); C0.x += f.x; C0.y += f.y;
                f = __half22float2(a1); C1.x += f.x; C1.y += f.y;
                f = __half22float2(a2); C2.x += f.x; C2.y += f.y;
                f = __half22float2(a3); C3.x += f.x; C3.y += f.y;
            }
            float cs0 = C0.x + C0.y, cs1 = C1.x + C1.y;
            float cs2 = C2.x + C2.y, cs3 = C3.x + C3.y;
            cs0 += __shfl_xor_sync(0xFFFFFFFFu, cs0, 1);
            cs1 += __shfl_xor_sync(0xFFFFFFFFu, cs1, 1);
            cs2 += __shfl_xor_sync(0xFFFFFFFFu, cs2, 1);
            cs3 += __shfl_xor_sync(0xFFFFFFFFu, cs3, 1);
            // epi A (batch kh)
            {
                float pre = (kh ? cs1 : cs0) + pxA;
                float zg  = __fdividef(1.f, 1.f + __expf(-zrawA));
                float e2  = __expf(2.f * pre);
                float ht  = 1.f - __fdividef(2.f, e2 + 1.f);
                float hn  = fmaf(zg, ht - hownA, hownA);
                out[((size_t)(b0 + kh) * TT + t) * HH + j] = hn;
                float hp = pdA * hn;
                hownA = hp;
                hpre16[kh][j >> 6][j & 63] = __float2half(hp);
            }
            // epi B (batch kh + 2)
            {
                float pre = (kh ? cs3 : cs2) + pxB;
                float zg  = __fdividef(1.f, 1.f + __expf(-zrawB));
                float e2  = __expf(2.f * pre);
                float ht  = 1.f - __fdividef(2.f, e2 + 1.f);
                float hn  = fmaf(zg, ht - hownB, hownB);
                out[((size_t)(b0 + kh + 2) * TT + t) * HH + j] = hn;
                float hp = pdB * hn;
                hownB = hp;
                hpre16[kh + 2][j >> 6][j & 63] = __float2half(hp);
            }
            // rotate THEN reload (verified-safe double buffer)
            pzA = nzA; prA = nrA; pxA = nxA; pdA = ndA;
            pzB = nzB; prB = nrB; pxB = nxB; pdB = ndB;
            int t2 = (t + 2 < TT) ? t + 2 : TT - 1;
            int t3 = (t + 3 < TT) ? t + 3 : TT - 1;
            size_t oA = tbA + (size_t)t2 * 512;
            size_t oB = tbB + (size_t)t2 * 512;
            nzA = g_pre[oA];       nrA = g_pre[oA + 128];
            nxA = g_pre[oA + 256]; ndA = g_pre[tbA + (size_t)t3 * 512 + 384];
            nzB = g_pre[oB];       nrB = g_pre[oB + 128];
            nxB = g_pre[oB + 256]; ndB = g_pre[tbB + (size_t)t3 * 512 + 384];
        }
        __syncthreads();                                   // bar 2
    }
}

} // namespace

extern "C" void kernel_launch(void* const* d_in, const int* in_sizes, int n_in,
                              void* d_out, int out_size) {
    const float* inp = (const float*)d_in[0];
    const float* Wgx = (const float*)d_in[1];
    const float* bgx = (const float*)d_in[2];
    const float* Wgh = (const float*)d_in[3];
    const float* bgh = (const float*)d_in[4];
    const float* Wz  = (const float*)d_in[5];
    const float* bz  = (const float*)d_in[6];
    const float* Wr  = (const float*)d_in[7];
    const float* br  = (const float*)d_in[8];
    const float* Wh  = (const float*)d_in[9];
    const float* bh  = (const float*)d_in[10];
    float* out = (float*)d_out;

    act_kernel<<<NROW / 8, 256>>>(inp, Wgx, bgx);
    packw_kernel<<<56, 256>>>(Wz, Wr, Wh, Wgh);
    cudaFuncSetAttribute(gemm_kernel,
                         cudaFuncAttributeMaxDynamicSharedMemorySize, GEMM_SMEM);
    gemm_kernel<<<NROW / 128, 256, GEMM_SMEM>>>(bz, br, bh, bgh);
    scan_kernel<<<BB / 4, 256>>>(Wz, Wr, Wh, out);
}